// round 2
// baseline (speedup 1.0000x reference)
#include <cuda_runtime.h>

#define NUM_USERS 100000
#define NUM_ITEMS 50000
#define NN 150000          // N_NODES
#define NE 4000000         // N_EDGES
#define H 64
#define BATCH 100000
#define MLPH 32

// ---- scratch (allocation-free: __device__ globals) ----
__device__ __align__(256) float g_xa[NN * H];
__device__ __align__(256) float g_xb[NN * H];
__device__ __align__(256) float g_mean[NN * H];
__device__ int g_cnt[NN];
__device__ int g_off[NN + 1];
__device__ int g_cur[NN];
__device__ int g_srcs[NE];

// ============================================================
// 1) concat embeddings into g_xa, zero counters
// ============================================================
__global__ void k_concat_zero(const float* __restrict__ ue, const float* __restrict__ ie) {
    int i = blockIdx.x * blockDim.x + threadIdx.x;
    const int nu4 = NUM_USERS * H / 4;   // 1,600,000
    const int ni4 = NUM_ITEMS * H / 4;   //   800,000
    float4* xa = (float4*)g_xa;
    if (i < nu4) {
        xa[i] = ((const float4*)ue)[i];
    } else if (i < nu4 + ni4) {
        xa[i] = ((const float4*)ie)[i - nu4];
    }
    if (i < NN) g_cnt[i] = 0;
}

// ============================================================
// 2) degree count
// ============================================================
__global__ void k_count(const int* __restrict__ dst) {
    int i = blockIdx.x * blockDim.x + threadIdx.x;
    if (i < NE) atomicAdd(&g_cnt[dst[i]], 1);
}

// ============================================================
// 3) single-block exclusive scan of g_cnt -> g_off, copy to g_cur
// ============================================================
__global__ void k_scan() {
    __shared__ __align__(16) int sdata[1024];
    __shared__ int s_carry;
    int tid = threadIdx.x;
    if (tid == 0) s_carry = 0;
    __syncthreads();
    for (int base = 0; base < NN; base += 1024) {
        int i = base + tid;
        int v = (i < NN) ? g_cnt[i] : 0;
        sdata[tid] = v;
        __syncthreads();
        #pragma unroll
        for (int ofs = 1; ofs < 1024; ofs <<= 1) {
            int t = (tid >= ofs) ? sdata[tid - ofs] : 0;
            __syncthreads();
            sdata[tid] += t;
            __syncthreads();
        }
        int excl = sdata[tid] - v;
        if (i < NN) {
            int o = s_carry + excl;
            g_off[i] = o;
            g_cur[i] = o;
        }
        __syncthreads();
        if (tid == 1023) s_carry += sdata[1023];
        __syncthreads();
    }
    if (tid == 0) g_off[NN] = s_carry;
}

// ============================================================
// 4) bucket edges by dst (counting-sort scatter)
// ============================================================
__global__ void k_bucket(const int* __restrict__ src, const int* __restrict__ dst) {
    int i = blockIdx.x * blockDim.x + threadIdx.x;
    if (i < NE) {
        int p = atomicAdd(&g_cur[dst[i]], 1);
        g_srcs[p] = src[i];
    }
}

// ============================================================
// 5) mean aggregation: warp per node, two half-warps interleave edges
//    each of 16 lanes owns a float4 (64 cols total)
// ============================================================
__global__ void k_agg(const float* __restrict__ x) {
    int w = (blockIdx.x * blockDim.x + threadIdx.x) >> 5;
    if (w >= NN) return;
    int lane = threadIdx.x & 31;
    int half = lane >> 4;
    int l4 = lane & 15;
    int s = g_off[w];
    int e = g_off[w + 1];
    float4 acc = make_float4(0.f, 0.f, 0.f, 0.f);
    const float4* x4 = (const float4*)x;
    for (int i = s + half; i < e; i += 2) {
        int sn = g_srcs[i];
        float4 v = __ldg(&x4[sn * 16 + l4]);
        acc.x += v.x; acc.y += v.y; acc.z += v.z; acc.w += v.w;
    }
    acc.x += __shfl_xor_sync(0xffffffffu, acc.x, 16);
    acc.y += __shfl_xor_sync(0xffffffffu, acc.y, 16);
    acc.z += __shfl_xor_sync(0xffffffffu, acc.z, 16);
    acc.w += __shfl_xor_sync(0xffffffffu, acc.w, 16);
    int c = e - s;
    float inv = 1.0f / (float)(c > 1 ? c : 1);
    if (half == 0) {
        float4 m = make_float4(acc.x * inv, acc.y * inv, acc.z * inv, acc.w * inv);
        ((float4*)g_mean)[w * 16 + l4] = m;
    }
}

// ============================================================
// 6) fused linear: out = relu(mean@Wl + b + x@Wr), warp per node
// ============================================================
__global__ void k_lin(const float* __restrict__ xin, float* __restrict__ xout,
                      const float* __restrict__ Wl, const float* __restrict__ bl,
                      const float* __restrict__ Wr) {
    __shared__ __align__(16) float sWl[H * H];
    __shared__ __align__(16) float sWr[H * H];
    __shared__ __align__(16) float sb[H];
    __shared__ __align__(16) float srow[8][2][H];

    int tid = threadIdx.x;
    for (int i = tid; i < H * H; i += 256) {
        sWl[i] = Wl[i];
        sWr[i] = Wr[i];
    }
    if (tid < H) sb[tid] = bl[tid];
    __syncthreads();

    int wid = tid >> 5, lane = tid & 31;
    int nwarps = gridDim.x * 8;
    for (int n = blockIdx.x * 8 + wid; n < NN; n += nwarps) {
        float2 m2 = __ldg(&((const float2*)g_mean)[n * 32 + lane]);
        float2 x2 = __ldg(&((const float2*)xin)[n * 32 + lane]);
        *(float2*)&srow[wid][0][2 * lane] = m2;
        *(float2*)&srow[wid][1][2 * lane] = x2;
        __syncwarp();
        float2 o;
        o.x = sb[2 * lane];
        o.y = sb[2 * lane + 1];
        #pragma unroll 16
        for (int k = 0; k < H; k++) {
            float mk = srow[wid][0][k];
            float xk = srow[wid][1][k];
            float2 wl = ((const float2*)(sWl + k * H))[lane];
            float2 wr = ((const float2*)(sWr + k * H))[lane];
            o.x += mk * wl.x + xk * wr.x;
            o.y += mk * wl.y + xk * wr.y;
        }
        o.x = fmaxf(o.x, 0.f);
        o.y = fmaxf(o.y, 0.f);
        ((float2*)xout)[n * 32 + lane] = o;
        __syncwarp();
    }
}

// ============================================================
// 7) final MLP: warp per pair; h = relu(pair@W1+b1); out=clip(h@W2+b2)
// ============================================================
__global__ void k_mlp(const float* __restrict__ x,
                      const int* __restrict__ uid, const int* __restrict__ iid,
                      const float* __restrict__ W1, const float* __restrict__ b1,
                      const float* __restrict__ W2, const float* __restrict__ b2,
                      float* __restrict__ out) {
    __shared__ __align__(16) float sW1[2 * H * MLPH];   // 128x32
    __shared__ __align__(16) float sW2[MLPH];
    __shared__ __align__(16) float sb1[MLPH];
    __shared__ float sb2;
    __shared__ __align__(16) float spair[8][2 * H];

    int tid = threadIdx.x;
    for (int i = tid; i < 2 * H * MLPH; i += 256) sW1[i] = W1[i];
    if (tid < MLPH) { sW2[tid] = W2[tid]; sb1[tid] = b1[tid]; }
    if (tid == 0) sb2 = b2[0];
    __syncthreads();

    int wid = tid >> 5, lane = tid & 31;
    for (int i = blockIdx.x * 8 + wid; i < BATCH; i += gridDim.x * 8) {
        int u = __ldg(&uid[i]);
        int it = __ldg(&iid[i]) + NUM_USERS;
        const float4* ur = (const float4*)(x + (size_t)u * H);
        const float4* ir = (const float4*)(x + (size_t)it * H);
        if (lane < 16) {
            *(float4*)&spair[wid][lane * 4] = __ldg(&ur[lane]);
        } else {
            *(float4*)&spair[wid][64 + (lane - 16) * 4] = __ldg(&ir[lane - 16]);
        }
        __syncwarp();
        float h = sb1[lane];
        #pragma unroll 16
        for (int k = 0; k < 2 * H; k++) {
            h += spair[wid][k] * sW1[k * MLPH + lane];
        }
        h = fmaxf(h, 0.f);
        float r = h * sW2[lane];
        #pragma unroll
        for (int o = 16; o; o >>= 1) r += __shfl_xor_sync(0xffffffffu, r, o);
        if (lane == 0) out[i] = fminf(fmaxf(r + sb2, 1.0f), 5.0f);
        __syncwarp();
    }
}

// ============================================================
// launch
// ============================================================
extern "C" void kernel_launch(void* const* d_in, const int* in_sizes, int n_in,
                              void* d_out, int out_size) {
    (void)in_sizes; (void)n_in; (void)out_size;
    const int*   edge = (const int*)d_in[0];
    const int*   src  = edge;
    const int*   dst  = edge + NE;
    const int*   uid  = (const int*)d_in[1];
    const int*   iid  = (const int*)d_in[2];
    const float* ue   = (const float*)d_in[3];
    const float* ie   = (const float*)d_in[4];
    const float* Wl   = (const float*)d_in[5];
    const float* bl   = (const float*)d_in[6];
    const float* Wr   = (const float*)d_in[7];
    const float* W1   = (const float*)d_in[8];
    const float* b1   = (const float*)d_in[9];
    const float* W2   = (const float*)d_in[10];
    const float* b2   = (const float*)d_in[11];
    float* out = (float*)d_out;

    float *xa, *xb;
    cudaGetSymbolAddress((void**)&xa, g_xa);
    cudaGetSymbolAddress((void**)&xb, g_xb);

    // build x and CSR (reused across all 3 layers)
    k_concat_zero<<<(2400000 + 255) / 256, 256>>>(ue, ie);
    k_count<<<(NE + 255) / 256, 256>>>(dst);
    k_scan<<<1, 1024>>>();
    k_bucket<<<(NE + 255) / 256, 256>>>(src, dst);

    float* cur = xa;
    float* nxt = xb;
    for (int l = 0; l < 3; l++) {
        k_agg<<<(NN * 32 + 255) / 256, 256>>>(cur);
        k_lin<<<1480, 256>>>(cur, nxt, Wl + l * H * H, bl + l * H, Wr + l * H * H);
        float* t = cur; cur = nxt; nxt = t;
    }

    k_mlp<<<2048, 256>>>(cur, uid, iid, W1, b1, W2, b2, out);
}

// round 3
// speedup vs baseline: 1.2798x; 1.2798x over previous
#include <cuda_runtime.h>

#define NUM_USERS 100000
#define NUM_ITEMS 50000
#define NN 150000          // N_NODES
#define NE 4000000         // N_EDGES
#define H 64
#define BATCH 100000
#define MLPH 32
#define NTILES ((NN + 1023) / 1024)   // 147

// ---- scratch (allocation-free: __device__ globals) ----
__device__ __align__(256) float g_xa[NN * H];
__device__ __align__(256) float g_xb[NN * H];
__device__ int g_cnt[NN];
__device__ int g_off[NN + 1];
__device__ int g_cur[NN];
__device__ int g_srcs[NE];
__device__ int g_psum[NTILES];

// ============================================================
// 1) concat embeddings into g_xa, zero counters
// ============================================================
__global__ void k_concat_zero(const float* __restrict__ ue, const float* __restrict__ ie) {
    int i = blockIdx.x * blockDim.x + threadIdx.x;
    const int nu4 = NUM_USERS * H / 4;   // 1,600,000
    const int ni4 = NUM_ITEMS * H / 4;   //   800,000
    float4* xa = (float4*)g_xa;
    if (i < nu4) {
        xa[i] = ((const float4*)ue)[i];
    } else if (i < nu4 + ni4) {
        xa[i] = ((const float4*)ie)[i - nu4];
    }
    if (i < NN) g_cnt[i] = 0;
}

// ============================================================
// 2) degree count
// ============================================================
__global__ void k_count(const int* __restrict__ dst) {
    int i = blockIdx.x * blockDim.x + threadIdx.x;
    if (i < NE) atomicAdd(&g_cnt[dst[i]], 1);
}

// ============================================================
// 3a) per-tile block scan: exclusive within tile -> g_off, tile sum -> g_psum
// ============================================================
__global__ void k_scan1() {
    __shared__ __align__(16) int sdata[1024];
    int tid = threadIdx.x;
    int i = blockIdx.x * 1024 + tid;
    int v = (i < NN) ? g_cnt[i] : 0;
    sdata[tid] = v;
    __syncthreads();
    #pragma unroll
    for (int ofs = 1; ofs < 1024; ofs <<= 1) {
        int t = (tid >= ofs) ? sdata[tid - ofs] : 0;
        __syncthreads();
        sdata[tid] += t;
        __syncthreads();
    }
    if (i < NN) g_off[i] = sdata[tid] - v;     // exclusive within tile
    if (tid == 1023) g_psum[blockIdx.x] = sdata[1023];
}

// ============================================================
// 3b) scan the 147 tile sums (single block, 256 threads)
// ============================================================
__global__ void k_scan2() {
    __shared__ __align__(16) int sdata[256];
    int tid = threadIdx.x;
    int v = (tid < NTILES) ? g_psum[tid] : 0;
    sdata[tid] = v;
    __syncthreads();
    #pragma unroll
    for (int ofs = 1; ofs < 256; ofs <<= 1) {
        int t = (tid >= ofs) ? sdata[tid - ofs] : 0;
        __syncthreads();
        sdata[tid] += t;
        __syncthreads();
    }
    if (tid < NTILES) g_psum[tid] = sdata[tid] - v;  // exclusive
}

// ============================================================
// 3c) add tile offsets, replicate to g_cur, finalize g_off[NN]
// ============================================================
__global__ void k_scan3() {
    int i = blockIdx.x * blockDim.x + threadIdx.x;
    if (i < NN) {
        int o = g_off[i] + g_psum[blockIdx.x >> 2];   // 256 thr/blk -> 4 blk/tile
        g_off[i] = o;
        g_cur[i] = o;
    }
    if (i == 0) g_off[NN] = NE;
}

// ============================================================
// 4) bucket edges by dst (counting-sort scatter)
// ============================================================
__global__ void k_bucket(const int* __restrict__ src, const int* __restrict__ dst) {
    int i = blockIdx.x * blockDim.x + threadIdx.x;
    if (i < NE) {
        int p = atomicAdd(&g_cur[dst[i]], 1);
        g_srcs[p] = src[i];
    }
}

// ============================================================
// 5) fused SAGE layer: mean-gather + relu(mean@Wl + b + x@Wr)
//    warp per node, grid-stride
// ============================================================
__global__ void k_sage(const float* __restrict__ x, float* __restrict__ xout,
                       const float* __restrict__ Wl, const float* __restrict__ bl,
                       const float* __restrict__ Wr) {
    __shared__ __align__(16) float sWl[H * H];
    __shared__ __align__(16) float sWr[H * H];
    __shared__ __align__(16) float sb[H];
    __shared__ __align__(16) float srow[8][2][H];

    int tid = threadIdx.x;
    for (int i = tid; i < H * H; i += 256) {
        sWl[i] = Wl[i];
        sWr[i] = Wr[i];
    }
    if (tid < H) sb[tid] = bl[tid];
    __syncthreads();

    int wid = tid >> 5, lane = tid & 31;
    int half = lane >> 4;
    int l4 = lane & 15;
    const float4* x4 = (const float4*)x;
    int nwarps = gridDim.x * 8;

    for (int n = blockIdx.x * 8 + wid; n < NN; n += nwarps) {
        // ---- gather mean: two half-warps interleave the edge list ----
        int s = g_off[n];
        int e = g_off[n + 1];
        float4 acc = make_float4(0.f, 0.f, 0.f, 0.f);
        for (int i = s + half; i < e; i += 2) {
            int sn = g_srcs[i];
            float4 v = __ldg(&x4[sn * 16 + l4]);
            acc.x += v.x; acc.y += v.y; acc.z += v.z; acc.w += v.w;
        }
        acc.x += __shfl_xor_sync(0xffffffffu, acc.x, 16);
        acc.y += __shfl_xor_sync(0xffffffffu, acc.y, 16);
        acc.z += __shfl_xor_sync(0xffffffffu, acc.z, 16);
        acc.w += __shfl_xor_sync(0xffffffffu, acc.w, 16);
        int c = e - s;
        float inv = 1.0f / (float)(c > 1 ? c : 1);

        // ---- stage mean row + x row in shared ----
        if (half == 0) {
            float4 m = make_float4(acc.x * inv, acc.y * inv, acc.z * inv, acc.w * inv);
            *(float4*)&srow[wid][0][l4 * 4] = m;
        }
        float2 x2 = __ldg(&((const float2*)x)[n * 32 + lane]);
        *(float2*)&srow[wid][1][2 * lane] = x2;
        __syncwarp();

        // ---- GEMV: each lane owns 2 output cols ----
        float2 o;
        o.x = sb[2 * lane];
        o.y = sb[2 * lane + 1];
        #pragma unroll 16
        for (int k = 0; k < H; k++) {
            float mk = srow[wid][0][k];
            float xk = srow[wid][1][k];
            float2 wl = ((const float2*)(sWl + k * H))[lane];
            float2 wr = ((const float2*)(sWr + k * H))[lane];
            o.x += mk * wl.x + xk * wr.x;
            o.y += mk * wl.y + xk * wr.y;
        }
        o.x = fmaxf(o.x, 0.f);
        o.y = fmaxf(o.y, 0.f);
        ((float2*)xout)[n * 32 + lane] = o;
        __syncwarp();
    }
}

// ============================================================
// 6) final MLP: warp per pair; h = relu(pair@W1+b1); out=clip(h@W2+b2)
// ============================================================
__global__ void k_mlp(const float* __restrict__ x,
                      const int* __restrict__ uid, const int* __restrict__ iid,
                      const float* __restrict__ W1, const float* __restrict__ b1,
                      const float* __restrict__ W2, const float* __restrict__ b2,
                      float* __restrict__ out) {
    __shared__ __align__(16) float sW1[2 * H * MLPH];   // 128x32
    __shared__ __align__(16) float sW2[MLPH];
    __shared__ __align__(16) float sb1[MLPH];
    __shared__ float sb2;
    __shared__ __align__(16) float spair[8][2 * H];

    int tid = threadIdx.x;
    for (int i = tid; i < 2 * H * MLPH; i += 256) sW1[i] = W1[i];
    if (tid < MLPH) { sW2[tid] = W2[tid]; sb1[tid] = b1[tid]; }
    if (tid == 0) sb2 = b2[0];
    __syncthreads();

    int wid = tid >> 5, lane = tid & 31;
    for (int i = blockIdx.x * 8 + wid; i < BATCH; i += gridDim.x * 8) {
        int u = __ldg(&uid[i]);
        int it = __ldg(&iid[i]) + NUM_USERS;
        const float4* ur = (const float4*)(x + (size_t)u * H);
        const float4* ir = (const float4*)(x + (size_t)it * H);
        if (lane < 16) {
            *(float4*)&spair[wid][lane * 4] = __ldg(&ur[lane]);
        } else {
            *(float4*)&spair[wid][64 + (lane - 16) * 4] = __ldg(&ir[lane - 16]);
        }
        __syncwarp();
        float h = sb1[lane];
        #pragma unroll 16
        for (int k = 0; k < 2 * H; k++) {
            h += spair[wid][k] * sW1[k * MLPH + lane];
        }
        h = fmaxf(h, 0.f);
        float r = h * sW2[lane];
        #pragma unroll
        for (int o = 16; o; o >>= 1) r += __shfl_xor_sync(0xffffffffu, r, o);
        if (lane == 0) out[i] = fminf(fmaxf(r + sb2, 1.0f), 5.0f);
        __syncwarp();
    }
}

// ============================================================
// launch
// ============================================================
extern "C" void kernel_launch(void* const* d_in, const int* in_sizes, int n_in,
                              void* d_out, int out_size) {
    (void)in_sizes; (void)n_in; (void)out_size;
    const int*   edge = (const int*)d_in[0];
    const int*   src  = edge;
    const int*   dst  = edge + NE;
    const int*   uid  = (const int*)d_in[1];
    const int*   iid  = (const int*)d_in[2];
    const float* ue   = (const float*)d_in[3];
    const float* ie   = (const float*)d_in[4];
    const float* Wl   = (const float*)d_in[5];
    const float* bl   = (const float*)d_in[6];
    const float* Wr   = (const float*)d_in[7];
    const float* W1   = (const float*)d_in[8];
    const float* b1   = (const float*)d_in[9];
    const float* W2   = (const float*)d_in[10];
    const float* b2   = (const float*)d_in[11];
    float* out = (float*)d_out;

    float *xa, *xb;
    cudaGetSymbolAddress((void**)&xa, g_xa);
    cudaGetSymbolAddress((void**)&xb, g_xb);

    // build x and CSR (reused across all 3 layers)
    k_concat_zero<<<(2400000 + 255) / 256, 256>>>(ue, ie);
    k_count<<<(NE + 255) / 256, 256>>>(dst);
    k_scan1<<<NTILES, 1024>>>();
    k_scan2<<<1, 256>>>();
    k_scan3<<<NTILES * 4, 256>>>();
    k_bucket<<<(NE + 255) / 256, 256>>>(src, dst);

    float* cur = xa;
    float* nxt = xb;
    for (int l = 0; l < 3; l++) {
        k_sage<<<740, 256>>>(cur, nxt, Wl + l * H * H, bl + l * H, Wr + l * H * H);
        float* t = cur; cur = nxt; nxt = t;
    }

    k_mlp<<<2048, 256>>>(cur, uid, iid, W1, b1, W2, b2, out);
}